// round 7
// baseline (speedup 1.0000x reference)
#include <cuda_runtime.h>
#include <cuda_bf16.h>
#include <math.h>

#define N_   2
#define H_   96
#define W_   96
#define HWp  9216      // H_*W_

typedef unsigned long long u64;

__device__ __forceinline__ u64 pack2(float lo, float hi) {
    u64 r; asm("mov.b64 %0, {%1, %2};" : "=l"(r) : "f"(lo), "f"(hi)); return r;
}
__device__ __forceinline__ void ffma2(u64 &d, u64 a, u64 b) {
    asm("fma.rn.f32x2 %0, %1, %2, %0;" : "+l"(d) : "l"(a), "l"(b));
}
__device__ __forceinline__ float2 unpack2(u64 v) {
    float2 f; asm("mov.b64 {%0, %1}, %2;" : "=f"(f.x), "=f"(f.y) : "l"(v)); return f;
}

// ---------------- scratch (device globals; allocation-free) ----------------
__device__ float g_xh   [N_*64*HWp];
__device__ float g_xhT  [N_*HWp*64];     // NHWC
__device__ float g_tmplT[N_*HWp*64];     // NHWC
__device__ float g_pin0 [N_*64*HWp];     // conv_in partials
__device__ float g_pin1 [N_*64*HWp];
__device__ float g_omzE0[N_*27*HWp];     // offset-conv partials (z)
__device__ float g_omzE1[N_*27*HWp];
__device__ float g_omzU0[N_*27*HWp];
__device__ float g_omzU1[N_*27*HWp];
__device__ float g_omhE0[N_*27*HWp];     // offset-conv partials (h)
__device__ float g_omhE1[N_*27*HWp];
__device__ float g_omhU0[N_*27*HWp];
__device__ float g_omhU1[N_*27*HWp];
__device__ float g_ze   [N_*64*HWp];
__device__ float g_zu   [N_*64*HWp];
__device__ float g_re   [N_*64*HWp];
__device__ float g_ru   [N_*64*HWp];
__device__ float g_reT  [N_*HWp*64];     // NHWC
__device__ float g_ruT  [N_*HWp*64];     // NHWC
__device__ float g_xenh [N_*64*HWp];
__device__ float g_pout0[N_*256*HWp];    // conv_out partials
__device__ float g_pout1[N_*256*HWp];
__device__ float g_wR   [4*9*128*64];    // rearranged dcn weights (t,k,c,co)

// ============================================================================
// prep: rearrange 4 dcn weight tensors (co,c,k) -> (k,c,co). 1152 blocks x 256.
// ============================================================================
__global__ __launch_bounds__(256)
void prep_weights_kernel(const float* __restrict__ w0, const float* __restrict__ w1,
                         const float* __restrict__ w2, const float* __restrict__ w3,
                         float* __restrict__ wR)
{
    int idx = blockIdx.x * 256 + threadIdx.x;       // 0 .. 294911
    int t   = idx / 73728;
    int r   = idx - t * 73728;                      // input-linear: co*1152 + c*9 + k
    int co  = r / 1152;
    int rem = r - co * 1152;
    int c   = rem / 9;
    int k   = rem - c * 9;
    const float* src = (t == 0) ? w0 : (t == 1) ? w1 : (t == 2) ? w2 : w3;
    wR[t * 73728 + k * 8192 + c * 64 + co] = src[r];
}

// ============================================================================
// NCHW -> NHWC transpose (64 channels).
// ============================================================================
__global__ __launch_bounds__(64)
void transpose_nhwc_kernel(const float* __restrict__ in, float* __restrict__ out)
{
    const int n = blockIdx.y;
    const int y = blockIdx.x;
    const int c = (int)threadIdx.x;
    const float* src = in  + ((size_t)n * 64 + c) * HWp + y * W_;
    float*       dst = out + ((size_t)n * HWp + y * W_) * 64 + c;
#pragma unroll 4
    for (int x = 0; x < W_; x++)
        dst[(size_t)x * 64] = src[x];
}

// ============================================================================
// conv3x3 partial: computes a half-cin partial sum (no bias).
// grid.z bits: 0=n, 1=half, 2=chain. Block 128 thr, 32x8 tile, 8 couts, 2 px.
// ============================================================================
struct CArgs {
    const float* srcH[2];    // source base per cin-half
    const float* wt;
    float* outP[2];          // partial output per half
};

template<int CINL, int CINT>
__global__ __launch_bounds__(128, 6)
void conv3x3_partial(CArgs c0, CArgs c1, int COUT, int nStrideCh)
{
    const int zb    = blockIdx.z;
    const int n     = zb & 1;
    const int half  = (zb >> 1) & 1;
    const CArgs A   = (zb >> 2) ? c1 : c0;
    const float* src0 = A.srcH[half];
    float* outP       = A.outP[half];

    const int tile = blockIdx.x;            // 36 tiles: 3 x, 12 y
    const int co0  = blockIdx.y * 8;
    const int tx0  = (tile % 3) * 32;
    const int ty0  = (tile / 3) * 8;
    const int tid  = threadIdx.x;
    const int lx   = tid & 31;
    const int ry   = (tid >> 5) * 2;

    __shared__ float  sPatch[4][10][36];
    __shared__ float2 sW2[4][9][4];

    u64 acc2[4][2];
#pragma unroll
    for (int i = 0; i < 4; i++) { acc2[i][0] = 0ull; acc2[i][1] = 0ull; }

    for (int ci0 = 0; ci0 < CINL; ci0 += 4) {
        __syncthreads();
#pragma unroll
        for (int it = 0; it < 11; it++) {
            int idx = tid + it * 128;
            if (idx < 1360) {
                int cc  = idx / 340;
                int rem = idx - cc * 340;
                int rr  = rem / 34;
                int col = rem - rr * 34;
                int gy = ty0 + rr - 1;
                int gx = tx0 + col - 1;
                float v = 0.f;
                if ((unsigned)gy < (unsigned)H_ && (unsigned)gx < (unsigned)W_) {
                    int c = ci0 + cc;
                    v = src0[((size_t)n * nStrideCh + c) * HWp + gy * W_ + gx];
                }
                sPatch[cc][rr][col] = v;
            }
        }
        {
            float* sWf = (float*)sW2;
            for (int i = tid; i < 288; i += 128) {
                int cc  = i / 72;
                int rem = i - cc * 72;
                int co  = rem / 9;
                int k   = rem - co * 9;
                float wv = 0.f;
                if (co0 + co < COUT)
                    wv = A.wt[((size_t)(co0 + co) * CINT + half * CINL + ci0 + cc) * 9 + k];
                sWf[(cc * 9 + k) * 8 + co] = wv;
            }
        }
        __syncthreads();

#pragma unroll
        for (int cc = 0; cc < 4; cc++) {
            u64 pb[4][3];
#pragma unroll
            for (int dr = 0; dr < 4; dr++)
#pragma unroll
                for (int dc = 0; dc < 3; dc++) {
                    float v = sPatch[cc][ry + dr][lx + dc];
                    pb[dr][dc] = pack2(v, v);
                }
#pragma unroll
            for (int ky = 0; ky < 3; ky++)
#pragma unroll
                for (int kx = 0; kx < 3; kx++) {
                    const u64* w2p = (const u64*)sW2[cc][ky * 3 + kx];
#pragma unroll
                    for (int co2 = 0; co2 < 4; co2++) {
                        u64 w = w2p[co2];
                        ffma2(acc2[co2][0], w, pb[ky][kx]);
                        ffma2(acc2[co2][1], w, pb[ky + 1][kx]);
                    }
                }
        }
    }

#pragma unroll
    for (int px = 0; px < 2; px++) {
        int gy = ty0 + ry + px;
        int gp = gy * W_ + tx0 + lx;
#pragma unroll
        for (int co2 = 0; co2 < 4; co2++) {
            float2 t = unpack2(acc2[co2][px]);
            int coA = co0 + co2 * 2;
            if (coA < COUT)
                outP[((size_t)n * COUT + coA) * HWp + gp] = t.x;
            if (coA + 1 < COUT)
                outP[((size_t)n * COUT + coA + 1) * HWp + gp] = t.y;
        }
    }
}

// ============================================================================
// combiners: out = pa + pb + bias[c]   (xh variant also writes NHWC)
// ============================================================================
__global__ __launch_bounds__(256)
void combine_xh_kernel(const float* __restrict__ pa, const float* __restrict__ pb,
                       const float* __restrict__ bias,
                       float* __restrict__ outN, float* __restrict__ outT)
{
    int i4 = blockIdx.x * 256 + threadIdx.x;        // 294912 float4s
    float4 a = ((const float4*)pa)[i4];
    float4 b = ((const float4*)pb)[i4];
    int i = i4 * 4;
    int c = (i / HWp) & 63;
    int n = i / (64 * HWp);
    int p = i - (i / HWp) * HWp;
    float bs = bias[c];
    float4 v = make_float4(a.x + b.x + bs, a.y + b.y + bs, a.z + b.z + bs, a.w + b.w + bs);
    ((float4*)outN)[i4] = v;
    float* dst = outT + ((size_t)n * HWp + p) * 64 + c;
    dst[0]      = v.x;
    dst[64]     = v.y;
    dst[128]    = v.z;
    dst[192]    = v.w;
}

__global__ __launch_bounds__(256)
void combine_out_kernel(const float* __restrict__ pa, const float* __restrict__ pb,
                        const float* __restrict__ bias, float* __restrict__ out)
{
    int i4 = blockIdx.x * 256 + threadIdx.x;        // 1179648 float4s
    float4 a = ((const float4*)pa)[i4];
    float4 b = ((const float4*)pb)[i4];
    int i = i4 * 4;
    int c = (i / HWp) & 255;
    float bs = bias[c];
    ((float4*)out)[i4] = make_float4(a.x + b.x + bs, a.y + b.y + bs,
                                     a.z + b.z + bs, a.w + b.w + bs);
}

// ============================================================================
// Deformable conv, c-split: 256 thr = 2 channel-halves x 128 px (16x8 tile).
// 32 couts/block f32x2-packed (16 pairs). Weights from prearranged wR staged
// per-k as float4 into 16KB smem (aliased by the 16KB partial-acc exchange).
// om is consumed as two conv partials + bias (no combine pass needed).
// MODE 0: out = sigmoid(acc+b).  MODE 1: out = (1-z)*t + z*tanh(acc+b).
// ============================================================================
struct DcnArgs {
    const float *A, *B;          // NHWC gather sources (64 ch each)
    const float *omA, *omB;      // om partials, NCHW 27 ch
    const float *ob;             // offset-conv bias (27)
    const float *wR;             // (9,128,64) rearranged weights
    const float *bias;           // (64)
    const float *t, *z;          // MODE 1
    float *out;                  // NCHW
};

template<int MODE>
__global__ __launch_bounds__(256, 3)
void dcn_kernel(DcnArgs d0, DcnArgs d1)
{
    extern __shared__ float sW[];           // 4096 floats = 16KB (alias: exchange)
    const int zb   = blockIdx.z;
    const int n    = zb & 1;
    const DcnArgs a = (zb >> 1) ? d1 : d0;
    const int co0  = blockIdx.y * 32;
    const int tile = blockIdx.x;            // 72 tiles (6 x, 12 y), 16x8 px
    const int tx0  = (tile % 6) * 16;
    const int ty0  = (tile / 6) * 8;
    const int tid  = threadIdx.x;
    const int pxid = tid & 127;
    const int half = tid >> 7;
    const int lx   = pxid & 15;
    const int ly   = pxid >> 4;
    const int x    = tx0 + lx;
    const int y    = ty0 + ly;
    const int P    = y * W_ + x;

    u64 acc[16];
#pragma unroll
    for (int i = 0; i < 16; i++) acc[i] = 0ull;

    const float* omA = a.omA + (size_t)n * 27 * HWp + P;
    const float* omB = a.omB + (size_t)n * 27 * HWp + P;
    const float* gsrc = (half ? a.B : a.A) + (size_t)n * HWp * 64;

    for (int k = 0; k < 9; k++) {
        __syncthreads();
        {   // stage 128x32 weight slice: wR[k][c][co0..co0+31] -> sW[c*32+co]
            const float4* wk = (const float4*)(a.wR + (size_t)k * 8192) + (co0 >> 2);
#pragma unroll
            for (int it = 0; it < 4; it++) {
                int i4 = tid + it * 256;            // 0..1023
                int c  = i4 >> 3;
                int j  = i4 & 7;
                ((float4*)sW)[c * 8 + j] = wk[c * 16 + j];
            }
        }
        __syncthreads();

        const int ky = k / 3 - 1, kx = k % 3 - 1;
        float dy = omA[(size_t)k * HWp]        + omB[(size_t)k * HWp]        + a.ob[k];
        float dx = omA[(size_t)(9 + k) * HWp]  + omB[(size_t)(9 + k) * HWp]  + a.ob[9 + k];
        float mm = omA[(size_t)(18 + k) * HWp] + omB[(size_t)(18 + k) * HWp] + a.ob[18 + k];
        float mask = 1.f / (1.f + __expf(-mm));

        float py = (float)(y + ky) + dy;
        float px = (float)(x + kx) + dx;
        float y0f = floorf(py), x0f = floorf(px);
        float wy = py - y0f, wx = px - x0f;
        int iy0 = (int)y0f, ix0 = (int)x0f;
        int iy1 = iy0 + 1,  ix1 = ix0 + 1;
        bool vy0 = (iy0 >= 0) & (iy0 < H_);
        bool vy1 = (iy1 >= 0) & (iy1 < H_);
        bool vx0 = (ix0 >= 0) & (ix0 < W_);
        bool vx1 = (ix1 >= 0) & (ix1 < W_);
        int yc0 = min(max(iy0, 0), H_ - 1), yc1 = min(max(iy1, 0), H_ - 1);
        int xc0 = min(max(ix0, 0), W_ - 1), xc1 = min(max(ix1, 0), W_ - 1);
        int o00 = (yc0 * W_ + xc0) * 64, o01 = (yc0 * W_ + xc1) * 64;
        int o10 = (yc1 * W_ + xc0) * 64, o11 = (yc1 * W_ + xc1) * 64;
        float W00 = (vy0 & vx0) ? (1.f - wy) * (1.f - wx) * mask : 0.f;
        float W01 = (vy0 & vx1) ? (1.f - wy) * wx * mask : 0.f;
        float W10 = (vy1 & vx0) ? wy * (1.f - wx) * mask : 0.f;
        float W11 = (vy1 & vx1) ? wy * wx * mask : 0.f;

#pragma unroll 2
        for (int cc = 0; cc < 16; cc++) {
            const float* base = gsrc + cc * 4;
            float4 v00 = *(const float4*)(base + o00);
            float4 v01 = *(const float4*)(base + o01);
            float4 v10 = *(const float4*)(base + o10);
            float4 v11 = *(const float4*)(base + o11);
            float sv[4];
            sv[0] = W00*v00.x + W01*v01.x + W10*v10.x + W11*v11.x;
            sv[1] = W00*v00.y + W01*v01.y + W10*v10.y + W11*v11.y;
            sv[2] = W00*v00.z + W01*v01.z + W10*v10.z + W11*v11.z;
            sv[3] = W00*v00.w + W01*v01.w + W10*v10.w + W11*v11.w;
#pragma unroll
            for (int ch = 0; ch < 4; ch++) {
                u64 ss = pack2(sv[ch], sv[ch]);
                const u64* wp = (const u64*)(sW + (half * 64 + cc * 4 + ch) * 32);
#pragma unroll
                for (int cp = 0; cp < 16; cp++) ffma2(acc[cp], wp[cp], ss);
            }
        }
    }

    // exchange partial accumulators (half1 -> half0) in aliased smem
    __syncthreads();
    u64* sEx = (u64*)sW;                    // 2048 u64 = 16KB
    if (half == 1) {
#pragma unroll
        for (int cp = 0; cp < 16; cp++) sEx[pxid * 16 + cp] = acc[cp];
    }
    __syncthreads();
    if (half == 0) {
#pragma unroll
        for (int cp = 0; cp < 16; cp++) {
            float2 m = unpack2(acc[cp]);
            float2 o = unpack2(sEx[pxid * 16 + cp]);
            float v0 = m.x + o.x + a.bias[co0 + cp * 2];
            float v1 = m.y + o.y + a.bias[co0 + cp * 2 + 1];
            size_t oi0 = ((size_t)n * 64 + co0 + cp * 2) * HWp + P;
            if (MODE == 0) {
                a.out[oi0]       = 1.f / (1.f + __expf(-v0));
                a.out[oi0 + HWp] = 1.f / (1.f + __expf(-v1));
            } else {
                float z0 = a.z[oi0],       t0 = a.t[oi0];
                float z1 = a.z[oi0 + HWp], t1 = a.t[oi0 + HWp];
                a.out[oi0]       = (1.f - z0) * t0 + z0 * tanhf(v0);
                a.out[oi0 + HWp] = (1.f - z1) * t1 + z1 * tanhf(v1);
            }
        }
    }
}

// ============================================================================
// ncf: 7x7 (radius 3, dilation 2) correlation + softmax + sample. Chain-merged.
// ============================================================================
struct NcfArgs {
    const float *f1, *f2;
    float *out, *out_nhwc;
};

__global__ __launch_bounds__(256)
void ncf_kernel(NcfArgs a0, NcfArgs a1)
{
    extern __shared__ float sm[];
    float* sTile = sm;                 // 8960 floats
    float* sExch = sm;                 // alias: 6272
    float* sWgt  = sm + 8960;          // 6272

    const int chain = blockIdx.y >> 1;
    const int n     = blockIdx.y & 1;
    const NcfArgs A = chain ? a1 : a0;

    const int tile = blockIdx.x;       // 72 tiles (6 x, 12 y)
    const int tx0  = (tile % 6) * 16;
    const int ty0  = (tile / 6) * 8;
    const int tid  = threadIdx.x;
    const int pix  = tid & 127;
    const int half = tid >> 7;
    const int lx   = pix & 15;
    const int ly   = pix >> 4;
    const int x    = tx0 + lx;
    const int y    = ty0 + ly;
    const int p    = y * W_ + x;

    const float* F1 = A.f1 + (size_t)n * 64 * HWp;
    const float* F2 = A.f2 + (size_t)n * 64 * HWp;

    float corr[49];
#pragma unroll
    for (int k = 0; k < 49; k++) corr[k] = 0.f;

    for (int j = 0; j < 4; j++) {
        __syncthreads();
        for (int i = tid; i < 8960; i += 256) {
            int hb  = i / 4480;
            int rem = i - hb * 4480;
            int c   = rem / 560;
            int rc  = rem - c * 560;
            int rr  = rc / 28;
            int col = rc - rr * 28;
            int gy = ty0 + rr - 6, gx = tx0 + col - 6;
            int gc = hb * 32 + j * 8 + c;
            float v = 0.f;
            if ((unsigned)gy < (unsigned)H_ && (unsigned)gx < (unsigned)W_)
                v = F2[(size_t)gc * HWp + gy * W_ + gx];
            sTile[i] = v;
        }
        __syncthreads();
        const float* myT = sTile + half * 4480;
#pragma unroll
        for (int c = 0; c < 8; c++) {
            float f1v = F1[(size_t)(half * 32 + j * 8 + c) * HWp + p];
            const float* trow = myT + c * 560 + ly * 28 + lx;
#pragma unroll
            for (int k = 0; k < 49; k++)
                corr[k] += f1v * trow[(k / 7) * 56 + (k % 7) * 2];
        }
    }

    __syncthreads();
    if (half == 1) {
#pragma unroll
        for (int k = 0; k < 49; k++) sExch[pix * 49 + k] = corr[k];
    }
    __syncthreads();
    if (half == 0) {
        float tot[49];
        float m = -1e30f;
#pragma unroll
        for (int k = 0; k < 49; k++) {
            tot[k] = (corr[k] + sExch[pix * 49 + k]) * 0.125f;
            m = fmaxf(m, tot[k]);
        }
        float sum = 0.f;
#pragma unroll
        for (int k = 0; k < 49; k++) { tot[k] = __expf(tot[k] - m); sum += tot[k]; }
        float inv = 1.f / sum;
#pragma unroll
        for (int k = 0; k < 49; k++) sWgt[pix * 49 + k] = tot[k] * inv;
    }
    __syncthreads();

    float w[49];
#pragma unroll
    for (int k = 0; k < 49; k++) w[k] = sWgt[pix * 49 + k];

    for (int j = 0; j < 4; j++) {
        __syncthreads();
        for (int i = tid; i < 8960; i += 256) {
            int hb  = i / 4480;
            int rem = i - hb * 4480;
            int c   = rem / 560;
            int rc  = rem - c * 560;
            int rr  = rc / 28;
            int col = rc - rr * 28;
            int gy = ty0 + rr - 6, gx = tx0 + col - 6;
            int gc = hb * 32 + j * 8 + c;
            float v = 0.f;
            if ((unsigned)gy < (unsigned)H_ && (unsigned)gx < (unsigned)W_)
                v = F2[(size_t)gc * HWp + gy * W_ + gx];
            sTile[i] = v;
        }
        __syncthreads();
        const float* myT = sTile + half * 4480;
        float res[8];
#pragma unroll
        for (int c = 0; c < 8; c++) {
            const float* trow = myT + c * 560 + ly * 28 + lx;
            float s = 0.f;
#pragma unroll
            for (int k = 0; k < 49; k++)
                s += w[k] * trow[(k / 7) * 56 + (k % 7) * 2];
            res[c] = s;
            A.out[((size_t)n * 64 + half * 32 + j * 8 + c) * HWp + p] = s;
        }
        float* dst = A.out_nhwc + ((size_t)n * HWp + p) * 64 + half * 32 + j * 8;
        *(float4*)dst       = make_float4(res[0], res[1], res[2], res[3]);
        *(float4*)(dst + 4) = make_float4(res[4], res[5], res[6], res[7]);
    }
}

// ============================================================================
// launch
// ============================================================================
extern "C" void kernel_launch(void* const* d_in, const int* in_sizes, int n_in,
                              void* d_out, int out_size)
{
    (void)in_sizes; (void)n_in; (void)out_size;
    const float* x    = (const float*)d_in[0];
    const float* tmpl = (const float*)d_in[1];
    const float* w_in = (const float*)d_in[2];
    const float* b_in = (const float*)d_in[3];
    const float* w_out= (const float*)d_in[4];
    const float* b_out= (const float*)d_in[5];
    const float* ezw  = (const float*)d_in[6];
    const float* ezb  = (const float*)d_in[7];
    const float* ezow = (const float*)d_in[8];
    const float* ezob = (const float*)d_in[9];
    const float* ehw  = (const float*)d_in[10];
    const float* ehb  = (const float*)d_in[11];
    const float* ehow = (const float*)d_in[12];
    const float* ehob = (const float*)d_in[13];
    const float* uzw  = (const float*)d_in[14];
    const float* uzb  = (const float*)d_in[15];
    const float* uzow = (const float*)d_in[16];
    const float* uzob = (const float*)d_in[17];
    const float* uhw  = (const float*)d_in[18];
    const float* uhb  = (const float*)d_in[19];
    const float* uhow = (const float*)d_in[20];
    const float* uhob = (const float*)d_in[21];

    float *xh, *xhT, *tmplT, *pin0, *pin1;
    float *omzE0, *omzE1, *omzU0, *omzU1, *omhE0, *omhE1, *omhU0, *omhU1;
    float *ze, *zu, *re, *ru, *reT, *ruT, *xenh, *pout0, *pout1, *wR;
    cudaGetSymbolAddress((void**)&xh,    g_xh);
    cudaGetSymbolAddress((void**)&xhT,   g_xhT);
    cudaGetSymbolAddress((void**)&tmplT, g_tmplT);
    cudaGetSymbolAddress((void**)&pin0,  g_pin0);
    cudaGetSymbolAddress((void**)&pin1,  g_pin1);
    cudaGetSymbolAddress((void**)&omzE0, g_omzE0);
    cudaGetSymbolAddress((void**)&omzE1, g_omzE1);
    cudaGetSymbolAddress((void**)&omzU0, g_omzU0);
    cudaGetSymbolAddress((void**)&omzU1, g_omzU1);
    cudaGetSymbolAddress((void**)&omhE0, g_omhE0);
    cudaGetSymbolAddress((void**)&omhE1, g_omhE1);
    cudaGetSymbolAddress((void**)&omhU0, g_omhU0);
    cudaGetSymbolAddress((void**)&omhU1, g_omhU1);
    cudaGetSymbolAddress((void**)&ze,    g_ze);
    cudaGetSymbolAddress((void**)&zu,    g_zu);
    cudaGetSymbolAddress((void**)&re,    g_re);
    cudaGetSymbolAddress((void**)&ru,    g_ru);
    cudaGetSymbolAddress((void**)&reT,   g_reT);
    cudaGetSymbolAddress((void**)&ruT,   g_ruT);
    cudaGetSymbolAddress((void**)&xenh,  g_xenh);
    cudaGetSymbolAddress((void**)&pout0, g_pout0);
    cudaGetSymbolAddress((void**)&pout1, g_pout1);
    cudaGetSymbolAddress((void**)&wR,    g_wR);

    float* out_main = (float*)d_out;
    float* out_nt   = out_main + (size_t)N_ * 256 * HWp;

    const int NCF_SMEM = (8960 + 6272) * 4;
    const int DCN_SMEM = 4096 * 4;          // 16KB
    cudaFuncSetAttribute(ncf_kernel, cudaFuncAttributeMaxDynamicSharedMemorySize, NCF_SMEM);

    // L0: weight prep (also shifts ncu -s 5 to land on dcn_z)
    prep_weights_kernel<<<1152, 256>>>(ezw, uzw, ehw, uhw, wR);

    // L1: tmpl -> NHWC
    transpose_nhwc_kernel<<<dim3(H_, 2), 64>>>(tmpl, tmplT);

    // L2: conv_in partials (cin-split 256 -> 2x128)
    {
        CArgs c{{x, x + 128 * HWp}, w_in, {pin0, pin1}};
        conv3x3_partial<128, 256><<<dim3(36, 8, 4), 128>>>(c, c, 64, 256);
    }

    // L3: xh = pin0 + pin1 + b_in (NCHW + NHWC)
    combine_xh_kernel<<<1152, 256>>>(pin0, pin1, b_in, xh, xhT);

    // L4: offset convs for z (both chains, cin-split)
    {
        CArgs ce{{tmpl, xh}, ezow, {omzE0, omzE1}};
        CArgs cu{{xh, tmpl}, uzow, {omzU0, omzU1}};
        conv3x3_partial<64, 128><<<dim3(36, 4, 8), 128>>>(ce, cu, 27, 64);
    }

    // L5: dcn z-gates (both chains)  <-- ncu -s 5 lands here
    {
        DcnArgs de{tmplT, xhT, omzE0, omzE1, ezob, wR + 0 * 73728, ezb, nullptr, nullptr, ze};
        DcnArgs du{xhT, tmplT, omzU0, omzU1, uzob, wR + 1 * 73728, uzb, nullptr, nullptr, zu};
        dcn_kernel<0><<<dim3(72, 2, 4), 256, DCN_SMEM>>>(de, du);
    }

    // L6: ncf (both chains)
    {
        NcfArgs ae{xh, tmpl, re, reT};
        NcfArgs au{tmpl, xh, ru, ruT};
        ncf_kernel<<<dim3(72, 4), 256, NCF_SMEM>>>(ae, au);
    }

    // L7: offset convs for h (both chains, cin-split)
    {
        CArgs ce{{re, xh}, ehow, {omhE0, omhE1}};
        CArgs cu{{ru, tmpl}, uhow, {omhU0, omhU1}};
        conv3x3_partial<64, 128><<<dim3(36, 4, 8), 128>>>(ce, cu, 27, 64);
    }

    // L8: dcn h + GRU blend (both chains)
    {
        DcnArgs de{reT, xhT, omhE0, omhE1, ehob, wR + 2 * 73728, ehb, xh, ze, xenh};
        DcnArgs du{ruT, tmplT, omhU0, omhU1, uhob, wR + 3 * 73728, uhb, tmpl, zu, out_nt};
        dcn_kernel<1><<<dim3(72, 2, 4), 256, DCN_SMEM>>>(de, du);
    }

    // L9: conv_out partials (cin-split 64 -> 2x32)
    {
        CArgs c{{xenh, xenh + 32 * HWp}, w_out, {pout0, pout1}};
        conv3x3_partial<32, 64><<<dim3(36, 32, 4), 128>>>(c, c, 256, 64);
    }

    // L10: out = pout0 + pout1 + b_out
    combine_out_kernel<<<4608, 256>>>(pout0, pout1, b_out, out_main);
}

// round 8
// speedup vs baseline: 1.6336x; 1.6336x over previous
#include <cuda_runtime.h>
#include <cuda_bf16.h>
#include <math.h>

#define N_   2
#define H_   96
#define W_   96
#define HWp  9216      // H_*W_

typedef unsigned long long u64;

__device__ __forceinline__ u64 pack2(float lo, float hi) {
    u64 r; asm("mov.b64 %0, {%1, %2};" : "=l"(r) : "f"(lo), "f"(hi)); return r;
}
__device__ __forceinline__ void ffma2(u64 &d, u64 a, u64 b) {
    asm("fma.rn.f32x2 %0, %1, %2, %0;" : "+l"(d) : "l"(a), "l"(b));
}
__device__ __forceinline__ float2 unpack2(u64 v) {
    float2 f; asm("mov.b64 {%0, %1}, %2;" : "=f"(f.x), "=f"(f.y) : "l"(v)); return f;
}

// ---------------- scratch (device globals; allocation-free) ----------------
__device__ float g_xh   [N_*64*HWp];
__device__ float g_xhT  [N_*HWp*64];     // NHWC
__device__ float g_tmplT[N_*HWp*64];     // NHWC
__device__ float g_om_ze[N_*27*HWp];
__device__ float g_om_zu[N_*27*HWp];
__device__ float g_om_he[N_*27*HWp];
__device__ float g_om_hu[N_*27*HWp];
__device__ float g_ze   [N_*64*HWp];
__device__ float g_zu   [N_*64*HWp];
__device__ float g_re   [N_*64*HWp];
__device__ float g_ru   [N_*64*HWp];
__device__ float g_reT  [N_*HWp*64];     // NHWC
__device__ float g_ruT  [N_*HWp*64];     // NHWC
__device__ float g_xenh [N_*64*HWp];
__device__ float g_wR   [4*9*128*64];    // rearranged dcn weights (t,k,c,co)

// ============================================================================
// prep: rearrange 4 dcn weight tensors (co,c,k) -> (k,c,co).
// ============================================================================
__global__ __launch_bounds__(256)
void prep_weights_kernel(const float* __restrict__ w0, const float* __restrict__ w1,
                         const float* __restrict__ w2, const float* __restrict__ w3,
                         float* __restrict__ wR)
{
    int idx = blockIdx.x * 256 + threadIdx.x;       // 0 .. 294911
    int t   = idx / 73728;
    int r   = idx - t * 73728;                      // co*1152 + c*9 + k
    int co  = r / 1152;
    int rem = r - co * 1152;
    int c   = rem / 9;
    int k   = rem - c * 9;
    const float* src = (t == 0) ? w0 : (t == 1) ? w1 : (t == 2) ? w2 : w3;
    wR[t * 73728 + k * 8192 + c * 64 + co] = src[r];
}

// ============================================================================
// NCHW -> NHWC transpose (64 channels).
// ============================================================================
__global__ __launch_bounds__(64)
void transpose_nhwc_kernel(const float* __restrict__ in, float* __restrict__ out)
{
    const int n = blockIdx.y;
    const int y = blockIdx.x;
    const int c = (int)threadIdx.x;
    const float* src = in  + ((size_t)n * 64 + c) * HWp + y * W_;
    float*       dst = out + ((size_t)n * HWp + y * W_) * 64 + c;
#pragma unroll 4
    for (int x = 0; x < W_; x++)
        dst[(size_t)x * 64] = src[x];
}

// ============================================================================
// conv3x3, SAME, NCHW, f32x2 over cout pairs, 4 px/thread, double-buffered
// patch prefetch (one sync per stage). Block 128 thr, 32x16 tile, 8 couts.
// Input = channel-concat: [0,CA) from inA, [CA,CIN) from inB.
// Optional NHWC dual output (COUT==64 path).
// ============================================================================
struct ConvArgs {
    const float *inA, *inB, *wt, *bias;
    float *out, *out_nhwc;
};

template<int CIN, int CA>
__global__ __launch_bounds__(128)
void conv3x3_kernel(ConvArgs a0, ConvArgs a1, int COUT)
{
    const int chain = blockIdx.z >> 1;
    const int n     = blockIdx.z & 1;
    const ConvArgs A = chain ? a1 : a0;

    const int tile = blockIdx.x;            // 18 tiles: 3 x, 6 y
    const int co0  = blockIdx.y * 8;
    const int tx0  = (tile % 3) * 32;
    const int ty0  = (tile / 3) * 16;
    const int tid  = threadIdx.x;
    const int lx   = tid & 31;
    const int ry   = (tid >> 5) * 4;        // 4 vertical px per thread

    __shared__ float sPatch[2][4][18][36];  // rows -1..16, cols -1..32 (pad)
    __shared__ float sW[2][4][9][8];        // [buf][cc][k][co]

    const int NS = CIN / 4;

    float pv[20];
    float wv[3];

    // ---- load stage s into regs ----
    auto dummy = 0; (void)dummy;
#define CONV_LDG(sidx)                                                          \
    {                                                                           \
        const int ci0 = (sidx) * 4;                                             \
        _Pragma("unroll")                                                       \
        for (int it = 0; it < 20; it++) {                                       \
            int idx = tid + it * 128;                                           \
            float v = 0.f;                                                      \
            if (idx < 2448) {                                                   \
                int cc  = idx / 612;                                            \
                int rem = idx - cc * 612;                                       \
                int rr  = rem / 34;                                             \
                int col = rem - rr * 34;                                        \
                int gy = ty0 + rr - 1, gx = tx0 + col - 1;                      \
                if ((unsigned)gy < (unsigned)H_ && (unsigned)gx < (unsigned)W_) { \
                    int c = ci0 + cc;                                           \
                    const float* src = (c < CA)                                 \
                        ? A.inA + ((size_t)n * CA + c) * HWp                    \
                        : A.inB + ((size_t)n * (CIN - CA) + (c - CA)) * HWp;    \
                    v = src[gy * W_ + gx];                                      \
                }                                                               \
            }                                                                   \
            pv[it] = v;                                                         \
        }                                                                       \
        _Pragma("unroll")                                                       \
        for (int it = 0; it < 3; it++) {                                        \
            int i = tid + it * 128;                                             \
            float v = 0.f;                                                      \
            if (i < 288) {                                                      \
                int cc = i / 72; int rem = i - cc * 72;                         \
                int co = rem / 9; int k = rem - co * 9;                         \
                if (co0 + co < COUT)                                            \
                    v = A.wt[((size_t)(co0 + co) * CIN + ci0 + cc) * 9 + k];    \
            }                                                                   \
            wv[it] = v;                                                         \
        }                                                                       \
    }

#define CONV_STS(buf)                                                           \
    {                                                                           \
        _Pragma("unroll")                                                       \
        for (int it = 0; it < 20; it++) {                                       \
            int idx = tid + it * 128;                                           \
            if (idx < 2448) {                                                   \
                int cc  = idx / 612;                                            \
                int rem = idx - cc * 612;                                       \
                int rr  = rem / 34;                                             \
                int col = rem - rr * 34;                                        \
                sPatch[buf][cc][rr][col] = pv[it];                              \
            }                                                                   \
        }                                                                       \
        _Pragma("unroll")                                                       \
        for (int it = 0; it < 3; it++) {                                        \
            int i = tid + it * 128;                                             \
            if (i < 288) {                                                      \
                int cc = i / 72; int rem = i - cc * 72;                         \
                int co = rem / 9; int k = rem - co * 9;                         \
                sW[buf][cc][k][co] = wv[it];                                    \
            }                                                                   \
        }                                                                       \
    }

    CONV_LDG(0);
    CONV_STS(0);
    __syncthreads();

    u64 acc2[4][4];                          // [co-pair][px]
#pragma unroll
    for (int i = 0; i < 4; i++)
#pragma unroll
        for (int j = 0; j < 4; j++) acc2[i][j] = 0ull;

    for (int s = 0; s < NS; s++) {
        const int b = s & 1;
        if (s + 1 < NS) CONV_LDG(s + 1);

#pragma unroll
        for (int cc = 0; cc < 4; cc++) {
            u64 pb[6][3];
#pragma unroll
            for (int dr = 0; dr < 6; dr++)
#pragma unroll
                for (int dc = 0; dc < 3; dc++) {
                    float v = sPatch[b][cc][ry + dr][lx + dc];
                    pb[dr][dc] = pack2(v, v);
                }
#pragma unroll
            for (int k = 0; k < 9; k++) {
                const int ky = k / 3, kx = k - ky * 3;
                const u64* wp = (const u64*)sW[b][cc][k];
                u64 w0 = wp[0], w1 = wp[1], w2 = wp[2], w3 = wp[3];
#pragma unroll
                for (int px = 0; px < 4; px++) {
                    ffma2(acc2[0][px], w0, pb[px + ky][kx]);
                    ffma2(acc2[1][px], w1, pb[px + ky][kx]);
                    ffma2(acc2[2][px], w2, pb[px + ky][kx]);
                    ffma2(acc2[3][px], w3, pb[px + ky][kx]);
                }
            }
        }

        if (s + 1 < NS) CONV_STS(b ^ 1);
        __syncthreads();
    }

#pragma unroll
    for (int px = 0; px < 4; px++) {
        float v[8];
#pragma unroll
        for (int co2 = 0; co2 < 4; co2++) {
            float2 t = unpack2(acc2[co2][px]);
            int coA = co0 + co2 * 2;
            v[co2 * 2]     = t.x + ((coA     < COUT) ? A.bias[coA]     : 0.f);
            v[co2 * 2 + 1] = t.y + ((coA + 1 < COUT) ? A.bias[coA + 1] : 0.f);
        }
        int gy = ty0 + ry + px;
        int gp = gy * W_ + tx0 + lx;
#pragma unroll
        for (int co = 0; co < 8; co++)
            if (co0 + co < COUT)
                A.out[((size_t)n * COUT + co0 + co) * HWp + gp] = v[co];
        if (A.out_nhwc) {   // COUT==64 path
            float* dst = A.out_nhwc + ((size_t)n * HWp + gp) * 64 + co0;
            *(float4*)dst       = make_float4(v[0], v[1], v[2], v[3]);
            *(float4*)(dst + 4) = make_float4(v[4], v[5], v[6], v[7]);
        }
    }
#undef CONV_LDG
#undef CONV_STS
}

// ============================================================================
// Deformable conv: gather-to-smem + register-tiled GEMM.
// Block 256 thr, 16x16 px tile, all 64 couts. Per (k, 32c-chunk):
//   gather: each thread (one pixel) samples 32 channels -> sS[32][256]
//   weights: wR[k][c][64co] -> sW duplicated (w,w) u64
//   GEMM: thread tile 8co x 8px (4 f32x2 px-pairs), 12 LDS : 32 FFMA2 per c.
// MODE 0: out = sigmoid(acc+b).  MODE 1: out = (1-z)*t + z*tanh(acc+b).
// ============================================================================
struct DcnArgs {
    const float *A, *B;          // NHWC gather sources (64 ch each)
    const float *om;             // NCHW, 27 ch (bias included by offset conv)
    const float *wR;             // (9,128,64) rearranged weights
    const float *bias;           // (64)
    const float *t, *z;          // MODE 1
    float *out;                  // NCHW
};

template<int MODE>
__global__ __launch_bounds__(256, 2)
void dcn_kernel(DcnArgs d0, DcnArgs d1)
{
    __shared__ float sS[32][256];            // 32 KB samples
    __shared__ u64   sW[32 * 64];            // 16 KB duplicated weights

    const int n    = blockIdx.z & 1;
    const DcnArgs a = (blockIdx.z >> 1) ? d1 : d0;
    const int tile = blockIdx.x;             // 36 tiles (6 x, 6 y) of 16x16
    const int tx0  = (tile % 6) * 16;
    const int ty0  = (tile / 6) * 16;
    const int tid  = threadIdx.x;
    const int lx   = tid & 15;
    const int ly   = tid >> 4;
    const int x    = tx0 + lx;
    const int y    = ty0 + ly;
    const int P    = y * W_ + x;
    const int cog  = tid >> 5;               // 0..7
    const int co8  = cog * 8;
    const int pxg  = tid & 31;
    const int px8  = pxg * 8;

    u64 acc[8][4];
#pragma unroll
    for (int i = 0; i < 8; i++)
#pragma unroll
        for (int j = 0; j < 4; j++) acc[i][j] = 0ull;

    const float* om = a.om + (size_t)n * 27 * HWp + P;
    const float* Ap = a.A  + (size_t)n * HWp * 64;
    const float* Bp = a.B  + (size_t)n * HWp * 64;

    for (int k = 0; k < 9; k++) {
        const int ky = k / 3 - 1, kx = k % 3 - 1;
        float dy = om[(size_t)k * HWp];
        float dx = om[(size_t)(9 + k) * HWp];
        float mm = om[(size_t)(18 + k) * HWp];
        float mask = 1.f / (1.f + __expf(-mm));

        float py = (float)(y + ky) + dy;
        float px = (float)(x + kx) + dx;
        float y0f = floorf(py), x0f = floorf(px);
        float wy = py - y0f, wx = px - x0f;
        int iy0 = (int)y0f, ix0 = (int)x0f;
        int iy1 = iy0 + 1,  ix1 = ix0 + 1;
        bool vy0 = (iy0 >= 0) & (iy0 < H_);
        bool vy1 = (iy1 >= 0) & (iy1 < H_);
        bool vx0 = (ix0 >= 0) & (ix0 < W_);
        bool vx1 = (ix1 >= 0) & (ix1 < W_);
        int yc0 = min(max(iy0, 0), H_ - 1), yc1 = min(max(iy1, 0), H_ - 1);
        int xc0 = min(max(ix0, 0), W_ - 1), xc1 = min(max(ix1, 0), W_ - 1);
        int o00 = (yc0 * W_ + xc0) * 64, o01 = (yc0 * W_ + xc1) * 64;
        int o10 = (yc1 * W_ + xc0) * 64, o11 = (yc1 * W_ + xc1) * 64;
        float W00 = (vy0 & vx0) ? (1.f - wy) * (1.f - wx) * mask : 0.f;
        float W01 = (vy0 & vx1) ? (1.f - wy) * wx * mask : 0.f;
        float W10 = (vy1 & vx0) ? wy * (1.f - wx) * mask : 0.f;
        float W11 = (vy1 & vx1) ? wy * wx * mask : 0.f;

        for (int ck = 0; ck < 4; ck++) {
            __syncthreads();                 // previous GEMM done reading
            // ---- gather 32 channels for this thread's pixel ----
            {
                const int cbase = ck * 32;
                const float* src = (cbase < 64) ? Ap : Bp;
                const int coff = cbase & 63;
#pragma unroll
                for (int q = 0; q < 8; q++) {
                    const float* bp = src + coff + q * 4;
                    float4 v00 = *(const float4*)(bp + o00);
                    float4 v01 = *(const float4*)(bp + o01);
                    float4 v10 = *(const float4*)(bp + o10);
                    float4 v11 = *(const float4*)(bp + o11);
                    sS[q * 4 + 0][tid] = W00*v00.x + W01*v01.x + W10*v10.x + W11*v11.x;
                    sS[q * 4 + 1][tid] = W00*v00.y + W01*v01.y + W10*v10.y + W11*v11.y;
                    sS[q * 4 + 2][tid] = W00*v00.z + W01*v01.z + W10*v10.z + W11*v11.z;
                    sS[q * 4 + 3][tid] = W00*v00.w + W01*v01.w + W10*v10.w + W11*v11.w;
                }
            }
            // ---- stage duplicated weights ----
            {
                const float4* wk = (const float4*)(a.wR + (size_t)k * 8192 + ck * 2048);
#pragma unroll
                for (int it = 0; it < 2; it++) {
                    int i4 = tid + it * 256;     // 0..511
                    float4 w = wk[i4];
                    int c   = i4 >> 4;
                    int co4 = (i4 & 15) * 4;
                    float4* dst = (float4*)(sW + c * 64 + co4);
                    dst[0] = make_float4(w.x, w.x, w.y, w.y);
                    dst[1] = make_float4(w.z, w.z, w.w, w.w);
                }
            }
            __syncthreads();
            // ---- GEMM: 8co x 8px per thread ----
#pragma unroll 2
            for (int c = 0; c < 32; c++) {
                const u64* wp = sW + c * 64 + co8;
                u64 w0 = wp[0], w1 = wp[1], w2 = wp[2], w3 = wp[3];
                u64 w4 = wp[4], w5 = wp[5], w6 = wp[6], w7 = wp[7];
                const u64* sp = (const u64*)(&sS[c][px8]);
                u64 s0 = sp[0], s1 = sp[1], s2 = sp[2], s3 = sp[3];
                ffma2(acc[0][0], w0, s0); ffma2(acc[0][1], w0, s1);
                ffma2(acc[0][2], w0, s2); ffma2(acc[0][3], w0, s3);
                ffma2(acc[1][0], w1, s0); ffma2(acc[1][1], w1, s1);
                ffma2(acc[1][2], w1, s2); ffma2(acc[1][3], w1, s3);
                ffma2(acc[2][0], w2, s0); ffma2(acc[2][1], w2, s1);
                ffma2(acc[2][2], w2, s2); ffma2(acc[2][3], w2, s3);
                ffma2(acc[3][0], w3, s0); ffma2(acc[3][1], w3, s1);
                ffma2(acc[3][2], w3, s2); ffma2(acc[3][3], w3, s3);
                ffma2(acc[4][0], w4, s0); ffma2(acc[4][1], w4, s1);
                ffma2(acc[4][2], w4, s2); ffma2(acc[4][3], w4, s3);
                ffma2(acc[5][0], w5, s0); ffma2(acc[5][1], w5, s1);
                ffma2(acc[5][2], w5, s2); ffma2(acc[5][3], w5, s3);
                ffma2(acc[6][0], w6, s0); ffma2(acc[6][1], w6, s1);
                ffma2(acc[6][2], w6, s2); ffma2(acc[6][3], w6, s3);
                ffma2(acc[7][0], w7, s0); ffma2(acc[7][1], w7, s1);
                ffma2(acc[7][2], w7, s2); ffma2(acc[7][3], w7, s3);
            }
        }
    }

    // ---- epilogue ----
#pragma unroll
    for (int co = 0; co < 8; co++) {
        float bs = a.bias[co8 + co];
        size_t ob = ((size_t)n * 64 + co8 + co) * HWp;
#pragma unroll
        for (int pp = 0; pp < 4; pp++) {
            float2 v = unpack2(acc[co][pp]);
            int pl = px8 + pp * 2;
            int P0 = (ty0 + (pl >> 4)) * W_ + tx0 + (pl & 15);
            float v0 = v.x + bs, v1 = v.y + bs;
            if (MODE == 0) {
                a.out[ob + P0]     = 1.f / (1.f + __expf(-v0));
                a.out[ob + P0 + 1] = 1.f / (1.f + __expf(-v1));
            } else {
                float z0 = a.z[ob + P0],     t0 = a.t[ob + P0];
                float z1 = a.z[ob + P0 + 1], t1 = a.t[ob + P0 + 1];
                a.out[ob + P0]     = (1.f - z0) * t0 + z0 * tanhf(v0);
                a.out[ob + P0 + 1] = (1.f - z1) * t1 + z1 * tanhf(v1);
            }
        }
    }
}

// ============================================================================
// ncf: 7x7 (radius 3, dilation 2) correlation + softmax + sample. Chain-merged.
// Block: 256 threads, 16x8 pixel tile; 2 threads/pixel split channels 32/32.
// Structured tile loader (no big div chains). Dual output NCHW + NHWC.
// ============================================================================
struct NcfArgs {
    const float *f1, *f2;
    float *out, *out_nhwc;
};

__device__ __forceinline__ void ncf_load_tile(const float* __restrict__ F2,
                                              float* __restrict__ sTile,
                                              int j, int tx0, int ty0, int tid)
{
    int w = tid >> 5, lane = tid & 31;
    if (lane < 28) {
        int gx = tx0 + lane - 6;
        bool vx = (unsigned)gx < (unsigned)W_;
#pragma unroll
        for (int pr2 = 0; pr2 < 2; pr2++) {
            int pr = w + pr2 * 8;            // 0..15: (hb, c)
            int hb = pr >> 3, c = pr & 7;
            int gc = hb * 32 + j * 8 + c;
            const float* src = F2 + (size_t)gc * HWp;
            float* dst = sTile + hb * 4480 + c * 560 + lane;
#pragma unroll
            for (int rr = 0; rr < 20; rr++) {
                int gy = ty0 + rr - 6;
                float v = 0.f;
                if (vx && (unsigned)gy < (unsigned)H_) v = src[gy * W_ + gx];
                dst[rr * 28] = v;
            }
        }
    }
}

__global__ __launch_bounds__(256)
void ncf_kernel(NcfArgs a0, NcfArgs a1)
{
    extern __shared__ float sm[];
    float* sTile = sm;                 // 8960 floats
    float* sExch = sm;                 // alias: 6272
    float* sWgt  = sm + 8960;          // 6272

    const int chain = blockIdx.y >> 1;
    const int n     = blockIdx.y & 1;
    const NcfArgs A = chain ? a1 : a0;

    const int tile = blockIdx.x;       // 72 tiles (6 x, 12 y)
    const int tx0  = (tile % 6) * 16;
    const int ty0  = (tile / 6) * 8;
    const int tid  = threadIdx.x;
    const int pix  = tid & 127;
    const int half = tid >> 7;
    const int lx   = pix & 15;
    const int ly   = pix >> 4;
    const int x    = tx0 + lx;
    const int y    = ty0 + ly;
    const int p    = y * W_ + x;

    const float* F1 = A.f1 + (size_t)n * 64 * HWp;
    const float* F2 = A.f2 + (size_t)n * 64 * HWp;

    float corr[49];
#pragma unroll
    for (int k = 0; k < 49; k++) corr[k] = 0.f;

    for (int j = 0; j < 4; j++) {
        __syncthreads();
        ncf_load_tile(F2, sTile, j, tx0, ty0, tid);
        __syncthreads();
        const float* myT = sTile + half * 4480;
#pragma unroll
        for (int c = 0; c < 8; c++) {
            float f1v = F1[(size_t)(half * 32 + j * 8 + c) * HWp + p];
            const float* trow = myT + c * 560 + ly * 28 + lx;
#pragma unroll
            for (int k = 0; k < 49; k++)
                corr[k] += f1v * trow[(k / 7) * 56 + (k % 7) * 2];
        }
    }

    __syncthreads();
    if (half == 1) {
#pragma unroll
        for (int k = 0; k < 49; k++) sExch[pix * 49 + k] = corr[k];
    }
    __syncthreads();
    if (half == 0) {
        float tot[49];
        float m = -1e30f;
#pragma unroll
        for (int k = 0; k < 49; k++) {
            tot[k] = (corr[k] + sExch[pix * 49 + k]) * 0.125f;   // 1/sqrt(64)
            m = fmaxf(m, tot[k]);
        }
        float sum = 0.f;
#pragma unroll
        for (int k = 0; k < 49; k++) { tot[k] = __expf(tot[k] - m); sum += tot[k]; }
        float inv = 1.f / sum;
#pragma unroll
        for (int k = 0; k < 49; k++) sWgt[pix * 49 + k] = tot[k] * inv;
    }
    __syncthreads();

    float w[49];
#pragma unroll
    for (int k = 0; k < 49; k++) w[k] = sWgt[pix * 49 + k];

    for (int j = 0; j < 4; j++) {
        __syncthreads();
        ncf_load_tile(F2, sTile, j, tx0, ty0, tid);
        __syncthreads();
        const float* myT = sTile + half * 4480;
        float res[8];
#pragma unroll
        for (int c = 0; c < 8; c++) {
            const float* trow = myT + c * 560 + ly * 28 + lx;
            float s = 0.f;
#pragma unroll
            for (int k = 0; k < 49; k++)
                s += w[k] * trow[(k / 7) * 56 + (k % 7) * 2];
            res[c] = s;
            A.out[((size_t)n * 64 + half * 32 + j * 8 + c) * HWp + p] = s;
        }
        float* dst = A.out_nhwc + ((size_t)n * HWp + p) * 64 + half * 32 + j * 8;
        *(float4*)dst       = make_float4(res[0], res[1], res[2], res[3]);
        *(float4*)(dst + 4) = make_float4(res[4], res[5], res[6], res[7]);
    }
}

// ============================================================================
// launch
// ============================================================================
extern "C" void kernel_launch(void* const* d_in, const int* in_sizes, int n_in,
                              void* d_out, int out_size)
{
    (void)in_sizes; (void)n_in; (void)out_size;
    const float* x    = (const float*)d_in[0];
    const float* tmpl = (const float*)d_in[1];
    const float* w_in = (const float*)d_in[2];
    const float* b_in = (const float*)d_in[3];
    const float* w_out= (const float*)d_in[4];
    const float* b_out= (const float*)d_in[5];
    const float* ezw  = (const float*)d_in[6];
    const float* ezb  = (const float*)d_in[7];
    const float* ezow = (const float*)d_in[8];
    const float* ezob = (const float*)d_in[9];
    const float* ehw  = (const float*)d_in[10];
    const float* ehb  = (const float*)d_in[11];
    const float* ehow = (const float*)d_in[12];
    const float* ehob = (const float*)d_in[13];
    const float* uzw  = (const float*)d_in[14];
    const float* uzb  = (const float*)d_in[15];
    const float* uzow = (const float*)d_in[16];
    const float* uzob = (const float*)d_in[17];
    const float* uhw  = (const float*)d_in[18];
    const float* uhb  = (const float*)d_in[19];
    const float* uhow = (const float*)d_in[20];
    const float* uhob = (const float*)d_in[21];

    float *xh, *xhT, *tmplT, *om_ze, *om_zu, *om_he, *om_hu;
    float *ze, *zu, *re, *ru, *reT, *ruT, *xenh, *wR;
    cudaGetSymbolAddress((void**)&xh,    g_xh);
    cudaGetSymbolAddress((void**)&xhT,   g_xhT);
    cudaGetSymbolAddress((void**)&tmplT, g_tmplT);
    cudaGetSymbolAddress((void**)&om_ze, g_om_ze);
    cudaGetSymbolAddress((void**)&om_zu, g_om_zu);
    cudaGetSymbolAddress((void**)&om_he, g_om_he);
    cudaGetSymbolAddress((void**)&om_hu, g_om_hu);
    cudaGetSymbolAddress((void**)&ze,    g_ze);
    cudaGetSymbolAddress((void**)&zu,    g_zu);
    cudaGetSymbolAddress((void**)&re,    g_re);
    cudaGetSymbolAddress((void**)&ru,    g_ru);
    cudaGetSymbolAddress((void**)&reT,   g_reT);
    cudaGetSymbolAddress((void**)&ruT,   g_ruT);
    cudaGetSymbolAddress((void**)&xenh,  g_xenh);
    cudaGetSymbolAddress((void**)&wR,    g_wR);

    float* out_main = (float*)d_out;                       // (2,256,96,96)
    float* out_nt   = out_main + (size_t)N_ * 256 * HWp;   // (2,64,96,96)

    const int NCF_SMEM = (8960 + 6272) * 4;
    cudaFuncSetAttribute(ncf_kernel, cudaFuncAttributeMaxDynamicSharedMemorySize, NCF_SMEM);

    // L0: dcn weight prep
    prep_weights_kernel<<<1152, 256>>>(ezw, uzw, ehw, uhw, wR);

    // L1: tmpl -> NHWC
    transpose_nhwc_kernel<<<dim3(H_, 2), 64>>>(tmpl, tmplT);

    // L2: xh = conv_in(x), dual NCHW + NHWC
    {
        ConvArgs a{x, x, w_in, b_in, xh, xhT};
        conv3x3_kernel<256,256><<<dim3(18, 8, 2), 128>>>(a, a, 64);
    }

    // L3: offset convs for z (both chains)
    {
        ConvArgs ae{tmpl, xh, ezow, ezob, om_ze, nullptr};
        ConvArgs au{xh, tmpl, uzow, uzob, om_zu, nullptr};
        conv3x3_kernel<128,64><<<dim3(18, 4, 4), 128>>>(ae, au, 27);
    }

    // L4: dcn z-gates (both chains)
    {
        DcnArgs de{tmplT, xhT, om_ze, wR + 0 * 73728, ezb, nullptr, nullptr, ze};
        DcnArgs du{xhT, tmplT, om_zu, wR + 1 * 73728, uzb, nullptr, nullptr, zu};
        dcn_kernel<0><<<dim3(36, 1, 4), 256>>>(de, du);
    }

    // L5: ncf (both chains)
    {
        NcfArgs ae{xh, tmpl, re, reT};
        NcfArgs au{tmpl, xh, ru, ruT};
        ncf_kernel<<<dim3(72, 4), 256, NCF_SMEM>>>(ae, au);
    }

    // L6: offset convs for h (both chains)
    {
        ConvArgs ae{re, xh, ehow, ehob, om_he, nullptr};
        ConvArgs au{ru, tmpl, uhow, uhob, om_hu, nullptr};
        conv3x3_kernel<128,64><<<dim3(18, 4, 4), 128>>>(ae, au, 27);
    }

    // L7: dcn h + GRU blend (both chains)
    {
        DcnArgs de{reT, xhT, om_he, wR + 2 * 73728, ehb, xh, ze, xenh};
        DcnArgs du{ruT, tmplT, om_hu, wR + 3 * 73728, uhb, tmpl, zu, out_nt};
        dcn_kernel<1><<<dim3(36, 1, 4), 256>>>(de, du);
    }

    // L8: out = conv_out(x_enh)
    {
        ConvArgs a{xenh, xenh, w_out, b_out, out_main, nullptr};
        conv3x3_kernel<64,64><<<dim3(18, 32, 2), 128>>>(a, a, 256);
    }
}